// round 2
// baseline (speedup 1.0000x reference)
#include <cuda_runtime.h>
#include <cuda_bf16.h>

#define N_NODES 100000
#define E_EDGES 1600000
#define D 128
#define BN_EPS 1e-5f

// Scratch (static device globals — allocation-free).
__device__ float4 g_agg4[(size_t)N_NODES * (D / 4)];   // 51.2 MB aggregate buffer
__device__ float  g_stats[2 * D];                      // [0:128) colsum, [128:256) colsumsq
__device__ float  g_scale[D];
__device__ float  g_shift[D];

// ---------------------------------------------------------------------------
// K0: zero agg + stats
// ---------------------------------------------------------------------------
__global__ void k_zero(int n_rows) {
    size_t i = (size_t)blockIdx.x * blockDim.x + threadIdx.x;
    size_t total = (size_t)n_rows * (D / 4);
    if (i < total) g_agg4[i] = make_float4(0.f, 0.f, 0.f, 0.f);
    if (blockIdx.x == 0 && threadIdx.x < 2 * D) g_stats[threadIdx.x] = 0.f;
}

// ---------------------------------------------------------------------------
// K1: SpMM scatter. One thread per (edge, 16B chunk): 32 threads cover an edge.
// Lanes of a warp share the same edge -> src/dst/val loads are uniform.
// NOTE: edge indices are int32 (JAX demotes int64 -> int32 with x64 disabled).
// ---------------------------------------------------------------------------
__global__ void k_spmm(const float4* __restrict__ x4,
                       const int* __restrict__ esrc,
                       const int* __restrict__ edst,
                       const float* __restrict__ eval,
                       long long n_edges, int n_rows) {
    size_t i = (size_t)blockIdx.x * blockDim.x + threadIdx.x;
    long long e = (long long)(i >> 5);
    if (e >= n_edges) return;
    int c = (int)(i & 31);

    int s = esrc[e];
    int d = edst[e];
    if ((unsigned)s >= (unsigned)n_rows || (unsigned)d >= (unsigned)n_rows) return;
    float v = eval[e];

    float4 xv = x4[(size_t)s * 32 + c];
    float4 m = make_float4(xv.x * v, xv.y * v, xv.z * v, xv.w * v);
    atomicAdd(&g_agg4[(size_t)d * 32 + c], m);   // RED.E.ADD.128 (sm_90+)
}

// ---------------------------------------------------------------------------
// K2: GEMM H = agg @ W + bias, fused column sum / sumsq for BatchNorm.
// Block: 128 rows x 128 cols, 256 threads, 8x8 register tile per thread.
// ---------------------------------------------------------------------------
#define MT 128
#define KT 32
#define SA_PAD 36   // multiple of 4 (float4-aligned rows)
#define SW_PAD 132  // multiple of 4

__global__ __launch_bounds__(256) void k_gemm(const float* __restrict__ W,
                                              const float* __restrict__ bias,
                                              float* __restrict__ H,
                                              int n_rows) {
    __shared__ float sA[MT * SA_PAD];   // 18.4 KB (reused for reduction)
    __shared__ float sW[KT * SW_PAD];   // 16.9 KB

    const float* A = (const float*)g_agg4;

    int tid = threadIdx.x;
    int tx = tid & 15;          // col group 0..15
    int ty = tid >> 4;          // row group 0..15
    int row0 = blockIdx.x * MT + ty * 8;
    int c0 = tx * 8;

    float acc[8][8];
#pragma unroll
    for (int i = 0; i < 8; i++)
#pragma unroll
        for (int j = 0; j < 8; j++) acc[i][j] = 0.f;

    for (int kc = 0; kc < D; kc += KT) {
        // load A tile: 128 rows x 32 k = 1024 float4, 4 per thread
#pragma unroll
        for (int q = 0; q < 4; q++) {
            int f = tid + 256 * q;
            int r = f >> 3;            // 0..127
            int kq = f & 7;            // 0..7 (float4 along k)
            int grow = blockIdx.x * MT + r;
            float4 v = make_float4(0.f, 0.f, 0.f, 0.f);
            if (grow < n_rows)
                v = *reinterpret_cast<const float4*>(&A[(size_t)grow * D + kc + kq * 4]);
            *reinterpret_cast<float4*>(&sA[r * SA_PAD + kq * 4]) = v;
        }
        // load W tile: 32 k x 128 cols = 1024 float4, 4 per thread
#pragma unroll
        for (int q = 0; q < 4; q++) {
            int f = tid + 256 * q;
            int r = f >> 5;            // k row 0..31
            int cq = f & 31;           // float4 along cols
            float4 v = *reinterpret_cast<const float4*>(&W[(size_t)(kc + r) * D + cq * 4]);
            *reinterpret_cast<float4*>(&sW[r * SW_PAD + cq * 4]) = v;
        }
        __syncthreads();

#pragma unroll
        for (int kk = 0; kk < KT; kk++) {
            float a[8], w[8];
#pragma unroll
            for (int i = 0; i < 8; i++) a[i] = sA[(ty * 8 + i) * SA_PAD + kk];
            float4 w0 = *reinterpret_cast<const float4*>(&sW[kk * SW_PAD + c0]);
            float4 w1 = *reinterpret_cast<const float4*>(&sW[kk * SW_PAD + c0 + 4]);
            w[0] = w0.x; w[1] = w0.y; w[2] = w0.z; w[3] = w0.w;
            w[4] = w1.x; w[5] = w1.y; w[6] = w1.z; w[7] = w1.w;
#pragma unroll
            for (int i = 0; i < 8; i++)
#pragma unroll
                for (int j = 0; j < 8; j++) acc[i][j] += a[i] * w[j];
        }
        __syncthreads();
    }

    // epilogue: bias, store H, per-thread column partial stats
    float4 b0 = *reinterpret_cast<const float4*>(&bias[c0]);
    float4 b1 = *reinterpret_cast<const float4*>(&bias[c0 + 4]);
    float bb[8] = {b0.x, b0.y, b0.z, b0.w, b1.x, b1.y, b1.z, b1.w};

    float csum[8], csq[8];
#pragma unroll
    for (int j = 0; j < 8; j++) { csum[j] = 0.f; csq[j] = 0.f; }

#pragma unroll
    for (int i = 0; i < 8; i++) {
        int row = row0 + i;
        if (row < n_rows) {
            float h[8];
#pragma unroll
            for (int j = 0; j < 8; j++) {
                h[j] = acc[i][j] + bb[j];
                csum[j] += h[j];
                csq[j] += h[j] * h[j];
            }
            float4 o0 = make_float4(h[0], h[1], h[2], h[3]);
            float4 o1 = make_float4(h[4], h[5], h[6], h[7]);
            *reinterpret_cast<float4*>(&H[(size_t)row * D + c0]) = o0;
            *reinterpret_cast<float4*>(&H[(size_t)row * D + c0 + 4]) = o1;
        }
    }

    // block reduction of stats in smem (reuse sA storage), then atomics
    __syncthreads();
    float* red = sA;   // needs 2*16*128 = 4096 floats <= 128*36
#pragma unroll
    for (int j = 0; j < 8; j++) {
        red[ty * D + c0 + j] = csum[j];
        red[2048 + ty * D + c0 + j] = csq[j];
    }
    __syncthreads();
    {
        int which = tid >> 7;           // 0: sum, 1: sumsq
        int c = tid & 127;
        float s = 0.f;
#pragma unroll
        for (int r = 0; r < 16; r++) s += red[which * 2048 + r * D + c];
        atomicAdd(&g_stats[which * D + c], s);
    }
}

// ---------------------------------------------------------------------------
// K3: finalize BN stats -> per-column scale/shift
// ---------------------------------------------------------------------------
__global__ void k_finalize(const float* __restrict__ gamma,
                           const float* __restrict__ beta,
                           float inv_n) {
    int c = threadIdx.x;
    float mean = g_stats[c] * inv_n;
    float var = g_stats[D + c] * inv_n - mean * mean;
    float inv = rsqrtf(var + BN_EPS);
    float sc = gamma[c] * inv;
    g_scale[c] = sc;
    g_shift[c] = beta[c] - mean * sc;
}

// ---------------------------------------------------------------------------
// K4: normalize in place
// ---------------------------------------------------------------------------
__global__ void k_norm(float4* __restrict__ out, int n_rows) {
    size_t i = (size_t)blockIdx.x * blockDim.x + threadIdx.x;
    size_t total = (size_t)n_rows * (D / 4);
    if (i >= total) return;
    int c4 = (int)(i & 31);
    float4 v = out[i];
    float4 sc = reinterpret_cast<const float4*>(g_scale)[c4];
    float4 sh = reinterpret_cast<const float4*>(g_shift)[c4];
    v.x = v.x * sc.x + sh.x;
    v.y = v.y * sc.y + sh.y;
    v.z = v.z * sc.z + sh.z;
    v.w = v.w * sc.w + sh.w;
    out[i] = v;
}

// ---------------------------------------------------------------------------
extern "C" void kernel_launch(void* const* d_in, const int* in_sizes, int n_in,
                              void* d_out, int out_size) {
    const float* x    = (const float*)d_in[0];      // [N,128]
    const int*   esrc = (const int*)d_in[1];        // [E] (int32 — JAX x64 disabled)
    const int*   edst = (const int*)d_in[2];        // [E]
    const float* eval = (const float*)d_in[3];      // [E]
    const float* W    = (const float*)d_in[4];      // [128,128]
    const float* bias = (const float*)d_in[5];      // [128]
    const float* gamm = (const float*)d_in[6];      // [128]
    const float* beta = (const float*)d_in[7];      // [128]
    float* out = (float*)d_out;

    int n_rows = in_sizes[0] / D;        // 100000
    long long n_edges = in_sizes[1];     // 1600000

    // K0: zero scratch
    {
        size_t items = (size_t)n_rows * (D / 4);
        int blocks = (int)((items + 255) / 256);
        k_zero<<<blocks, 256>>>(n_rows);
    }
    // K1: SpMM scatter with vector atomics
    {
        size_t items = (size_t)n_edges * 32;
        int blocks = (int)((items + 255) / 256);
        k_spmm<<<blocks, 256>>>((const float4*)x, esrc, edst, eval, n_edges, n_rows);
    }
    // K2: GEMM + bias + fused stats
    {
        int blocks = (n_rows + MT - 1) / MT;
        k_gemm<<<blocks, 256>>>(W, bias, out, n_rows);
    }
    // K3: finalize BN coefficients
    k_finalize<<<1, D>>>(gamm, beta, 1.0f / (float)n_rows);
    // K4: normalize
    {
        size_t items = (size_t)n_rows * (D / 4);
        int blocks = (int)((items + 255) / 256);
        k_norm<<<blocks, 256>>>((float4*)out, n_rows);
    }
}

// round 3
// speedup vs baseline: 1.4955x; 1.4955x over previous
#include <cuda_runtime.h>
#include <cuda_bf16.h>

#define N_NODES 100000
#define E_EDGES 1600000
#define D 128
#define BN_EPS 1e-5f
#define MAX_N 131072
#define MAX_E 2097152

// Scratch (static device globals — allocation-free).
__device__ float4 g_agg4[(size_t)N_NODES * (D / 4)];   // 51.2 MB aggregate
__device__ int    g_cnt[MAX_N];         // per-dst degree
__device__ int    g_excl[MAX_N];        // within-block exclusive scan
__device__ int    g_rowptr[MAX_N];      // CSR row start
__device__ int    g_woff[MAX_N];        // scatter write cursor
__device__ int    g_bsum[1024];         // block sums for scan
__device__ int    g_btop[1024];         // scanned block sums
__device__ int2   g_csr[MAX_E];         // packed (src, val-bits)
__device__ float  g_stats[2 * D];       // colsum / colsumsq
__device__ float  g_scale[D];
__device__ float  g_shift[D];

// ---------------- f32x2 packed-FMA helpers ----------------
__device__ __forceinline__ unsigned long long pack2(float lo, float hi) {
    unsigned long long r;
    asm("mov.b64 %0, {%1, %2};" : "=l"(r) : "f"(lo), "f"(hi));
    return r;
}
__device__ __forceinline__ void unpack2(unsigned long long v, float& lo, float& hi) {
    asm("mov.b64 {%0, %1}, %2;" : "=f"(lo), "=f"(hi) : "l"(v));
}
__device__ __forceinline__ void ffma2(unsigned long long& d,
                                      unsigned long long a,
                                      unsigned long long b) {
    asm("fma.rn.f32x2 %0, %1, %2, %0;" : "+l"(d) : "l"(a), "l"(b));
}

// ---------------------------------------------------------------------------
// K0: zero degree counters + stats
// ---------------------------------------------------------------------------
__global__ void k_zero_small(int n_rows) {
    int i = blockIdx.x * blockDim.x + threadIdx.x;
    if (i < n_rows) g_cnt[i] = 0;
    if (blockIdx.x == 0 && threadIdx.x < 2 * D) g_stats[threadIdx.x] = 0.f;
}

// ---------------------------------------------------------------------------
// K1: histogram of dst
// ---------------------------------------------------------------------------
__global__ void k_hist(const int* __restrict__ edst, int n_edges, int n_rows) {
    int e = blockIdx.x * blockDim.x + threadIdx.x;
    if (e >= n_edges) return;
    int d = edst[e];
    if ((unsigned)d < (unsigned)n_rows) atomicAdd(&g_cnt[d], 1);
}

// ---------------------------------------------------------------------------
// K2a: per-block scan of counts (256/block)
// ---------------------------------------------------------------------------
__global__ void k_scan_partial(int n_rows) {
    __shared__ int s[256];
    int i = blockIdx.x * 256 + threadIdx.x;
    int c = (i < n_rows) ? g_cnt[i] : 0;
    s[threadIdx.x] = c;
    __syncthreads();
#pragma unroll
    for (int off = 1; off < 256; off <<= 1) {
        int t = (threadIdx.x >= off) ? s[threadIdx.x - off] : 0;
        __syncthreads();
        s[threadIdx.x] += t;
        __syncthreads();
    }
    if (i < n_rows) g_excl[i] = s[threadIdx.x] - c;
    if (threadIdx.x == 255) g_bsum[blockIdx.x] = s[255];
}

// ---------------------------------------------------------------------------
// K2b: scan block sums (single block, up to 1024 blocks)
// ---------------------------------------------------------------------------
__global__ void k_scan_tops(int nb) {
    __shared__ int s[1024];
    int t = threadIdx.x;
    int v = (t < nb) ? g_bsum[t] : 0;
    s[t] = v;
    __syncthreads();
#pragma unroll
    for (int off = 1; off < 1024; off <<= 1) {
        int u = (t >= off) ? s[t - off] : 0;
        __syncthreads();
        s[t] += u;
        __syncthreads();
    }
    if (t < nb) g_btop[t] = s[t] - v;   // exclusive
}

// ---------------------------------------------------------------------------
// K2c: combine -> rowptr + write cursors
// ---------------------------------------------------------------------------
__global__ void k_scan_add(int n_rows) {
    int i = blockIdx.x * blockDim.x + threadIdx.x;
    if (i >= n_rows) return;
    int r = g_excl[i] + g_btop[i >> 8];
    g_rowptr[i] = r;
    g_woff[i] = r;
}

// ---------------------------------------------------------------------------
// K3: scatter edges into CSR slots (packed src+val)
// ---------------------------------------------------------------------------
__global__ void k_scatter(const int* __restrict__ esrc,
                          const int* __restrict__ edst,
                          const float* __restrict__ eval,
                          int n_edges, int n_rows) {
    int e = blockIdx.x * blockDim.x + threadIdx.x;
    if (e >= n_edges) return;
    int d = edst[e];
    if ((unsigned)d >= (unsigned)n_rows) return;
    int pos = atomicAdd(&g_woff[d], 1);
    int s = esrc[e];
    if ((unsigned)s >= (unsigned)n_rows) s = 0;  // defensive (val still applied; inputs are in-range)
    g_csr[pos] = make_int2(s, __float_as_int(eval[e]));
}

// ---------------------------------------------------------------------------
// K4: gather-reduce. One warp per node; lane owns one float4 chunk (128 cols).
// ---------------------------------------------------------------------------
__global__ __launch_bounds__(256) void k_gather(const float4* __restrict__ x4,
                                                int n_rows) {
    int warp = (blockIdx.x * blockDim.x + threadIdx.x) >> 5;
    if (warp >= n_rows) return;
    int lane = threadIdx.x & 31;

    int start = g_rowptr[warp];
    int deg = g_cnt[warp];
    int end = start + deg;

    float4 acc = make_float4(0.f, 0.f, 0.f, 0.f);
    int p = start;
    for (; p + 1 < end; p += 2) {
        int2 e0 = g_csr[p];
        int2 e1 = g_csr[p + 1];
        float4 a = x4[(size_t)e0.x * 32 + lane];
        float4 b = x4[(size_t)e1.x * 32 + lane];
        float v0 = __int_as_float(e0.y);
        float v1 = __int_as_float(e1.y);
        acc.x += a.x * v0 + b.x * v1;
        acc.y += a.y * v0 + b.y * v1;
        acc.z += a.z * v0 + b.z * v1;
        acc.w += a.w * v0 + b.w * v1;
    }
    if (p < end) {
        int2 e0 = g_csr[p];
        float4 a = x4[(size_t)e0.x * 32 + lane];
        float v0 = __int_as_float(e0.y);
        acc.x += a.x * v0;
        acc.y += a.y * v0;
        acc.z += a.z * v0;
        acc.w += a.w * v0;
    }
    g_agg4[(size_t)warp * 32 + lane] = acc;
}

// ---------------------------------------------------------------------------
// K5: GEMM H = agg @ W + bias, fused column stats. f32x2 packed FMA inner loop.
// ---------------------------------------------------------------------------
#define MT 128
#define KT 32
#define SA_PAD 36
#define SW_PAD 132

__global__ __launch_bounds__(256) void k_gemm(const float* __restrict__ W,
                                              const float* __restrict__ bias,
                                              float* __restrict__ H,
                                              int n_rows) {
    __shared__ float sA[MT * SA_PAD];
    __shared__ float sW[KT * SW_PAD];

    const float* A = (const float*)g_agg4;

    int tid = threadIdx.x;
    int tx = tid & 15;
    int ty = tid >> 4;
    int row0 = blockIdx.x * MT + ty * 8;
    int c0 = tx * 8;

    unsigned long long acc2[8][4];
#pragma unroll
    for (int i = 0; i < 8; i++)
#pragma unroll
        for (int j = 0; j < 4; j++) acc2[i][j] = 0ULL;

    for (int kc = 0; kc < D; kc += KT) {
#pragma unroll
        for (int q = 0; q < 4; q++) {
            int f = tid + 256 * q;
            int r = f >> 3;
            int kq = f & 7;
            int grow = blockIdx.x * MT + r;
            float4 v = make_float4(0.f, 0.f, 0.f, 0.f);
            if (grow < n_rows)
                v = *reinterpret_cast<const float4*>(&A[(size_t)grow * D + kc + kq * 4]);
            *reinterpret_cast<float4*>(&sA[r * SA_PAD + kq * 4]) = v;
        }
#pragma unroll
        for (int q = 0; q < 4; q++) {
            int f = tid + 256 * q;
            int r = f >> 5;
            int cq = f & 31;
            float4 v = *reinterpret_cast<const float4*>(&W[(size_t)(kc + r) * D + cq * 4]);
            *reinterpret_cast<float4*>(&sW[r * SW_PAD + cq * 4]) = v;
        }
        __syncthreads();

#pragma unroll
        for (int kk = 0; kk < KT; kk++) {
            unsigned long long aa[8];
#pragma unroll
            for (int i = 0; i < 8; i++) {
                float a = sA[(ty * 8 + i) * SA_PAD + kk];
                aa[i] = pack2(a, a);
            }
            float4 w0 = *reinterpret_cast<const float4*>(&sW[kk * SW_PAD + c0]);
            float4 w1 = *reinterpret_cast<const float4*>(&sW[kk * SW_PAD + c0 + 4]);
            unsigned long long wp[4];
            wp[0] = pack2(w0.x, w0.y);
            wp[1] = pack2(w0.z, w0.w);
            wp[2] = pack2(w1.x, w1.y);
            wp[3] = pack2(w1.z, w1.w);
#pragma unroll
            for (int i = 0; i < 8; i++)
#pragma unroll
                for (int j = 0; j < 4; j++) ffma2(acc2[i][j], aa[i], wp[j]);
        }
        __syncthreads();
    }

    float4 b0 = *reinterpret_cast<const float4*>(&bias[c0]);
    float4 b1 = *reinterpret_cast<const float4*>(&bias[c0 + 4]);
    float bb[8] = {b0.x, b0.y, b0.z, b0.w, b1.x, b1.y, b1.z, b1.w};

    float csum[8], csq[8];
#pragma unroll
    for (int j = 0; j < 8; j++) { csum[j] = 0.f; csq[j] = 0.f; }

#pragma unroll
    for (int i = 0; i < 8; i++) {
        int row = row0 + i;
        if (row < n_rows) {
            float h[8];
#pragma unroll
            for (int j = 0; j < 4; j++)
                unpack2(acc2[i][j], h[2 * j], h[2 * j + 1]);
#pragma unroll
            for (int j = 0; j < 8; j++) {
                h[j] += bb[j];
                csum[j] += h[j];
                csq[j] += h[j] * h[j];
            }
            float4 o0 = make_float4(h[0], h[1], h[2], h[3]);
            float4 o1 = make_float4(h[4], h[5], h[6], h[7]);
            *reinterpret_cast<float4*>(&H[(size_t)row * D + c0]) = o0;
            *reinterpret_cast<float4*>(&H[(size_t)row * D + c0 + 4]) = o1;
        }
    }

    __syncthreads();
    float* red = sA;   // 4096 floats needed
#pragma unroll
    for (int j = 0; j < 8; j++) {
        red[ty * D + c0 + j] = csum[j];
        red[2048 + ty * D + c0 + j] = csq[j];
    }
    __syncthreads();
    {
        int which = tid >> 7;
        int c = tid & 127;
        float s = 0.f;
#pragma unroll
        for (int r = 0; r < 16; r++) s += red[which * 2048 + r * D + c];
        atomicAdd(&g_stats[which * D + c], s);
    }
}

// ---------------------------------------------------------------------------
// K6: finalize BN stats
// ---------------------------------------------------------------------------
__global__ void k_finalize(const float* __restrict__ gamma,
                           const float* __restrict__ beta,
                           float inv_n) {
    int c = threadIdx.x;
    float mean = g_stats[c] * inv_n;
    float var = g_stats[D + c] * inv_n - mean * mean;
    float inv = rsqrtf(var + BN_EPS);
    float sc = gamma[c] * inv;
    g_scale[c] = sc;
    g_shift[c] = beta[c] - mean * sc;
}

// ---------------------------------------------------------------------------
// K7: normalize in place
// ---------------------------------------------------------------------------
__global__ void k_norm(float4* __restrict__ out, int n_rows) {
    size_t i = (size_t)blockIdx.x * blockDim.x + threadIdx.x;
    size_t total = (size_t)n_rows * (D / 4);
    if (i >= total) return;
    int c4 = (int)(i & 31);
    float4 v = out[i];
    float4 sc = reinterpret_cast<const float4*>(g_scale)[c4];
    float4 sh = reinterpret_cast<const float4*>(g_shift)[c4];
    v.x = v.x * sc.x + sh.x;
    v.y = v.y * sc.y + sh.y;
    v.z = v.z * sc.z + sh.z;
    v.w = v.w * sc.w + sh.w;
    out[i] = v;
}

// ---------------------------------------------------------------------------
extern "C" void kernel_launch(void* const* d_in, const int* in_sizes, int n_in,
                              void* d_out, int out_size) {
    const float* x    = (const float*)d_in[0];
    const int*   esrc = (const int*)d_in[1];
    const int*   edst = (const int*)d_in[2];
    const float* eval = (const float*)d_in[3];
    const float* W    = (const float*)d_in[4];
    const float* bias = (const float*)d_in[5];
    const float* gamm = (const float*)d_in[6];
    const float* beta = (const float*)d_in[7];
    float* out = (float*)d_out;

    int n_rows = in_sizes[0] / D;      // 100000
    int n_edges = in_sizes[1];         // 1600000
    int nb = (n_rows + 255) / 256;     // scan blocks (<=1024)

    k_zero_small<<<nb, 256>>>(n_rows);
    k_hist<<<(n_edges + 255) / 256, 256>>>(edst, n_edges, n_rows);
    k_scan_partial<<<nb, 256>>>(n_rows);
    k_scan_tops<<<1, 1024>>>(nb);
    k_scan_add<<<nb, 256>>>(n_rows);
    k_scatter<<<(n_edges + 255) / 256, 256>>>(esrc, edst, eval, n_edges, n_rows);
    k_gather<<<(n_rows * 32 + 255) / 256, 256>>>((const float4*)x, n_rows);
    k_gemm<<<(n_rows + MT - 1) / MT, 256>>>(W, bias, out, n_rows);
    k_finalize<<<1, D>>>(gamm, beta, 1.0f / (float)n_rows);
    {
        size_t items = (size_t)n_rows * (D / 4);
        k_norm<<<(int)((items + 255) / 256), 256>>>((float4*)out, n_rows);
    }
}

// round 4
// speedup vs baseline: 1.6536x; 1.1057x over previous
#include <cuda_runtime.h>
#include <cuda_bf16.h>

#define N_NODES 100000
#define E_EDGES 1600000
#define D 128
#define BN_EPS 1e-5f
#define MAX_N 131072
#define MAX_E 2097152

// Scratch (static device globals — allocation-free).
__device__ float4 g_agg4[(size_t)N_NODES * (D / 4)];   // 51.2 MB aggregate
__device__ int    g_cnt[MAX_N];         // per-dst degree
__device__ int    g_excl[MAX_N];        // within-block exclusive scan
__device__ int    g_woff2[MAX_N];       // scatter cursor (from 0)
__device__ int    g_bsum[1024];         // block sums for scan
__device__ int    g_btop[1024];         // scanned block sums (exclusive)
__device__ int2   g_csr[MAX_E];         // packed (src, val-bits)
__device__ float  g_stats[2 * D];       // colsum / colsumsq

// ---------------- f32x2 packed-FMA helpers ----------------
__device__ __forceinline__ unsigned long long pack2(float lo, float hi) {
    unsigned long long r;
    asm("mov.b64 %0, {%1, %2};" : "=l"(r) : "f"(lo), "f"(hi));
    return r;
}
__device__ __forceinline__ void unpack2(unsigned long long v, float& lo, float& hi) {
    asm("mov.b64 {%0, %1}, %2;" : "=f"(lo), "=f"(hi) : "l"(v));
}
__device__ __forceinline__ void ffma2(unsigned long long& d,
                                      unsigned long long a,
                                      unsigned long long b) {
    asm("fma.rn.f32x2 %0, %1, %2, %0;" : "+l"(d) : "l"(a), "l"(b));
}

// ---------------------------------------------------------------------------
// K0: zero degree counters + cursors + stats
// ---------------------------------------------------------------------------
__global__ void k_zero_small(int n_rows) {
    int i = blockIdx.x * blockDim.x + threadIdx.x;
    if (i < n_rows) { g_cnt[i] = 0; g_woff2[i] = 0; }
    if (blockIdx.x == 0 && threadIdx.x < 2 * D) g_stats[threadIdx.x] = 0.f;
}

// ---------------------------------------------------------------------------
// K1: histogram of dst
// ---------------------------------------------------------------------------
__global__ void k_hist(const int* __restrict__ edst, int n_edges, int n_rows) {
    int e = blockIdx.x * blockDim.x + threadIdx.x;
    if (e >= n_edges) return;
    int d = edst[e];
    if ((unsigned)d < (unsigned)n_rows) atomicAdd(&g_cnt[d], 1);
}

// ---------------------------------------------------------------------------
// K2a: per-block inclusive scan of counts -> exclusive partials
// ---------------------------------------------------------------------------
__global__ void k_scan_partial(int n_rows) {
    __shared__ int s[256];
    int i = blockIdx.x * 256 + threadIdx.x;
    int c = (i < n_rows) ? g_cnt[i] : 0;
    s[threadIdx.x] = c;
    __syncthreads();
#pragma unroll
    for (int off = 1; off < 256; off <<= 1) {
        int t = (threadIdx.x >= off) ? s[threadIdx.x - off] : 0;
        __syncthreads();
        s[threadIdx.x] += t;
        __syncthreads();
    }
    if (i < n_rows) g_excl[i] = s[threadIdx.x] - c;
    if (threadIdx.x == 255) g_bsum[blockIdx.x] = s[255];
}

// ---------------------------------------------------------------------------
// K2b: scan block sums (single block, up to 1024 blocks)
// ---------------------------------------------------------------------------
__global__ void k_scan_tops(int nb) {
    __shared__ int s[1024];
    int t = threadIdx.x;
    int v = (t < nb) ? g_bsum[t] : 0;
    s[t] = v;
    __syncthreads();
#pragma unroll
    for (int off = 1; off < 1024; off <<= 1) {
        int u = (t >= off) ? s[t - off] : 0;
        __syncthreads();
        s[t] += u;
        __syncthreads();
    }
    if (t < nb) g_btop[t] = s[t] - v;   // exclusive
}

// ---------------------------------------------------------------------------
// K3: scatter edges into CSR slots (rowptr computed inline)
// ---------------------------------------------------------------------------
__global__ void k_scatter(const int* __restrict__ esrc,
                          const int* __restrict__ edst,
                          const float* __restrict__ eval,
                          int n_edges, int n_rows) {
    int e = blockIdx.x * blockDim.x + threadIdx.x;
    if (e >= n_edges) return;
    int d = edst[e];
    if ((unsigned)d >= (unsigned)n_rows) return;
    int base = g_excl[d] + g_btop[d >> 8];
    int pos = base + atomicAdd(&g_woff2[d], 1);
    int s = esrc[e];
    if ((unsigned)s >= (unsigned)n_rows) s = 0;
    g_csr[pos] = make_int2(s, __float_as_int(eval[e]));
}

// ---------------------------------------------------------------------------
// K4: gather-reduce. One warp per node; lane owns one float4 chunk. 4x unroll.
// ---------------------------------------------------------------------------
__global__ __launch_bounds__(256) void k_gather(const float4* __restrict__ x4,
                                                int n_rows) {
    int warp = (blockIdx.x * blockDim.x + threadIdx.x) >> 5;
    if (warp >= n_rows) return;
    int lane = threadIdx.x & 31;

    int start = g_excl[warp] + g_btop[warp >> 8];
    int deg = g_cnt[warp];
    int end = start + deg;

    float4 acc = make_float4(0.f, 0.f, 0.f, 0.f);
    int p = start;
    for (; p + 3 < end; p += 4) {
        int2 e0 = g_csr[p];
        int2 e1 = g_csr[p + 1];
        int2 e2 = g_csr[p + 2];
        int2 e3 = g_csr[p + 3];
        float4 a = x4[(size_t)e0.x * 32 + lane];
        float4 b = x4[(size_t)e1.x * 32 + lane];
        float4 c = x4[(size_t)e2.x * 32 + lane];
        float4 d = x4[(size_t)e3.x * 32 + lane];
        float v0 = __int_as_float(e0.y);
        float v1 = __int_as_float(e1.y);
        float v2 = __int_as_float(e2.y);
        float v3 = __int_as_float(e3.y);
        acc.x += a.x * v0 + b.x * v1 + c.x * v2 + d.x * v3;
        acc.y += a.y * v0 + b.y * v1 + c.y * v2 + d.y * v3;
        acc.z += a.z * v0 + b.z * v1 + c.z * v2 + d.z * v3;
        acc.w += a.w * v0 + b.w * v1 + c.w * v2 + d.w * v3;
    }
    for (; p < end; p++) {
        int2 e0 = g_csr[p];
        float4 a = x4[(size_t)e0.x * 32 + lane];
        float v0 = __int_as_float(e0.y);
        acc.x += a.x * v0;
        acc.y += a.y * v0;
        acc.z += a.z * v0;
        acc.w += a.w * v0;
    }
    g_agg4[(size_t)warp * 32 + lane] = acc;
}

// ---------------------------------------------------------------------------
// K5: GEMM H = agg @ W + bias, fused column stats. Full-K smem, one sync.
// ---------------------------------------------------------------------------
#define MT 128
#define PAD 132
#define GEMM_SMEM (2 * 128 * PAD * sizeof(float))   // 135168 B

__global__ __launch_bounds__(256) void k_gemm(const float* __restrict__ W,
                                              const float* __restrict__ bias,
                                              float* __restrict__ H,
                                              int n_rows) {
    extern __shared__ float smem[];
    float* sA = smem;                 // 128 x PAD
    float* sW = smem + 128 * PAD;     // 128 x PAD

    const float* A = (const float*)g_agg4;

    int tid = threadIdx.x;
    int tx = tid & 15;
    int ty = tid >> 4;
    int row0 = blockIdx.x * MT + ty * 8;
    int c0 = tx * 8;

    // load full A tile (128 rows x 32 float4) and full W (128 x 32 float4)
#pragma unroll
    for (int q = 0; q < 16; q++) {
        int f = tid + 256 * q;
        int r = f >> 5;            // 0..127
        int kq = f & 31;           // float4 within row
        int grow = blockIdx.x * MT + r;
        float4 v = make_float4(0.f, 0.f, 0.f, 0.f);
        if (grow < n_rows)
            v = *reinterpret_cast<const float4*>(&A[(size_t)grow * D + kq * 4]);
        *reinterpret_cast<float4*>(&sA[r * PAD + kq * 4]) = v;
        float4 w = *reinterpret_cast<const float4*>(&W[(size_t)r * D + kq * 4]);
        *reinterpret_cast<float4*>(&sW[r * PAD + kq * 4]) = w;
    }
    __syncthreads();

    unsigned long long acc2[8][4];
#pragma unroll
    for (int i = 0; i < 8; i++)
#pragma unroll
        for (int j = 0; j < 4; j++) acc2[i][j] = 0ULL;

#pragma unroll 8
    for (int kk = 0; kk < D; kk++) {
        unsigned long long aa[8];
#pragma unroll
        for (int i = 0; i < 8; i++) {
            float a = sA[(ty * 8 + i) * PAD + kk];
            aa[i] = pack2(a, a);
        }
        float4 w0 = *reinterpret_cast<const float4*>(&sW[kk * PAD + c0]);
        float4 w1 = *reinterpret_cast<const float4*>(&sW[kk * PAD + c0 + 4]);
        unsigned long long wp[4];
        wp[0] = pack2(w0.x, w0.y);
        wp[1] = pack2(w0.z, w0.w);
        wp[2] = pack2(w1.x, w1.y);
        wp[3] = pack2(w1.z, w1.w);
#pragma unroll
        for (int i = 0; i < 8; i++)
#pragma unroll
            for (int j = 0; j < 4; j++) ffma2(acc2[i][j], aa[i], wp[j]);
    }

    float4 b0 = *reinterpret_cast<const float4*>(&bias[c0]);
    float4 b1 = *reinterpret_cast<const float4*>(&bias[c0 + 4]);
    float bb[8] = {b0.x, b0.y, b0.z, b0.w, b1.x, b1.y, b1.z, b1.w};

    float csum[8], csq[8];
#pragma unroll
    for (int j = 0; j < 8; j++) { csum[j] = 0.f; csq[j] = 0.f; }

#pragma unroll
    for (int i = 0; i < 8; i++) {
        int row = row0 + i;
        if (row < n_rows) {
            float h[8];
#pragma unroll
            for (int j = 0; j < 4; j++)
                unpack2(acc2[i][j], h[2 * j], h[2 * j + 1]);
#pragma unroll
            for (int j = 0; j < 8; j++) {
                h[j] += bb[j];
                csum[j] += h[j];
                csq[j] += h[j] * h[j];
            }
            float4 o0 = make_float4(h[0], h[1], h[2], h[3]);
            float4 o1 = make_float4(h[4], h[5], h[6], h[7]);
            *reinterpret_cast<float4*>(&H[(size_t)row * D + c0]) = o0;
            *reinterpret_cast<float4*>(&H[(size_t)row * D + c0 + 4]) = o1;
        }
    }

    // block reduction of stats in smem (reuse sA), then atomics
    __syncthreads();
    float* red = sA;   // 4096 floats needed
#pragma unroll
    for (int j = 0; j < 8; j++) {
        red[ty * D + c0 + j] = csum[j];
        red[2048 + ty * D + c0 + j] = csq[j];
    }
    __syncthreads();
    {
        int which = tid >> 7;
        int c = tid & 127;
        float s = 0.f;
#pragma unroll
        for (int r = 0; r < 16; r++) s += red[which * 2048 + r * D + c];
        atomicAdd(&g_stats[which * D + c], s);
    }
}

// ---------------------------------------------------------------------------
// K6: normalize in place (scale/shift computed per block from g_stats)
// ---------------------------------------------------------------------------
__global__ __launch_bounds__(256) void k_norm(float4* __restrict__ out,
                                              const float* __restrict__ gamma,
                                              const float* __restrict__ beta,
                                              float inv_n, int n_rows) {
    __shared__ float s_scale[D];
    __shared__ float s_shift[D];
    if (threadIdx.x < D) {
        int c = threadIdx.x;
        float mean = g_stats[c] * inv_n;
        float var = g_stats[D + c] * inv_n - mean * mean;
        float inv = rsqrtf(var + BN_EPS);
        float sc = gamma[c] * inv;
        s_scale[c] = sc;
        s_shift[c] = beta[c] - mean * sc;
    }
    __syncthreads();

    size_t total = (size_t)n_rows * (D / 4);
    size_t stride = (size_t)gridDim.x * blockDim.x;
    for (size_t i = (size_t)blockIdx.x * blockDim.x + threadIdx.x; i < total;
         i += stride) {
        int c4 = (int)(i & 31);
        float4 v = out[i];
        float4 sc = reinterpret_cast<const float4*>(s_scale)[c4];
        float4 sh = reinterpret_cast<const float4*>(s_shift)[c4];
        v.x = v.x * sc.x + sh.x;
        v.y = v.y * sc.y + sh.y;
        v.z = v.z * sc.z + sh.z;
        v.w = v.w * sc.w + sh.w;
        out[i] = v;
    }
}

// ---------------------------------------------------------------------------
extern "C" void kernel_launch(void* const* d_in, const int* in_sizes, int n_in,
                              void* d_out, int out_size) {
    const float* x    = (const float*)d_in[0];
    const int*   esrc = (const int*)d_in[1];
    const int*   edst = (const int*)d_in[2];
    const float* eval = (const float*)d_in[3];
    const float* W    = (const float*)d_in[4];
    const float* bias = (const float*)d_in[5];
    const float* gamm = (const float*)d_in[6];
    const float* beta = (const float*)d_in[7];
    float* out = (float*)d_out;

    int n_rows = in_sizes[0] / D;      // 100000
    int n_edges = in_sizes[1];         // 1600000
    int nb = (n_rows + 255) / 256;     // scan blocks (<=1024)

    static bool s_attr_done = false;
    if (!s_attr_done) {
        cudaFuncSetAttribute(k_gemm, cudaFuncAttributeMaxDynamicSharedMemorySize,
                             (int)GEMM_SMEM);
        s_attr_done = true;
    }

    k_zero_small<<<nb, 256>>>(n_rows);
    k_hist<<<(n_edges + 255) / 256, 256>>>(edst, n_edges, n_rows);
    k_scan_partial<<<nb, 256>>>(n_rows);
    k_scan_tops<<<1, 1024>>>(nb);
    k_scatter<<<(n_edges + 255) / 256, 256>>>(esrc, edst, eval, n_edges, n_rows);
    k_gather<<<(n_rows * 32 + 255) / 256, 256>>>((const float4*)x, n_rows);
    k_gemm<<<(n_rows + MT - 1) / MT, 256, GEMM_SMEM>>>(W, bias, out, n_rows);
    k_norm<<<1184, 256>>>((float4*)out, gamm, beta, 1.0f / (float)n_rows, n_rows);
}

// round 5
// speedup vs baseline: 1.6823x; 1.0174x over previous
#include <cuda_runtime.h>
#include <cuda_bf16.h>

#define N_NODES 100000
#define E_EDGES 1600000
#define D 128
#define BN_EPS 1e-5f
#define MAX_N 131072
#define MAX_E 2097152

// Scratch (static device globals — allocation-free).
__device__ float4 g_y4[(size_t)N_NODES * (D / 4)];   // 51.2 MB: y = x @ W
__device__ int    g_cnt[MAX_N];         // per-dst degree
__device__ int    g_excl[MAX_N];        // within-block exclusive scan
__device__ int    g_woff2[MAX_N];       // scatter cursor (from 0)
__device__ int    g_bsum[1024];         // block sums for scan
__device__ int    g_btop[1024];         // scanned block sums (exclusive)
__device__ int2   g_csr[MAX_E];         // packed (src, val-bits)
__device__ float  g_stats[2 * D];       // colsum / colsumsq of z

// ---------------- f32x2 packed-FMA helpers ----------------
__device__ __forceinline__ unsigned long long pack2(float lo, float hi) {
    unsigned long long r;
    asm("mov.b64 %0, {%1, %2};" : "=l"(r) : "f"(lo), "f"(hi));
    return r;
}
__device__ __forceinline__ void unpack2(unsigned long long v, float& lo, float& hi) {
    asm("mov.b64 {%0, %1}, %2;" : "=f"(lo), "=f"(hi) : "l"(v));
}
__device__ __forceinline__ void ffma2(unsigned long long& d,
                                      unsigned long long a,
                                      unsigned long long b) {
    asm("fma.rn.f32x2 %0, %1, %2, %0;" : "+l"(d) : "l"(a), "l"(b));
}

// ---------------------------------------------------------------------------
// K0: zero degree counters + cursors + stats
// ---------------------------------------------------------------------------
__global__ void k_zero_small(int n_rows) {
    int i = blockIdx.x * blockDim.x + threadIdx.x;
    if (i < n_rows) { g_cnt[i] = 0; g_woff2[i] = 0; }
    if (blockIdx.x == 0 && threadIdx.x < 2 * D) g_stats[threadIdx.x] = 0.f;
}

// ---------------------------------------------------------------------------
// K1: histogram of dst
// ---------------------------------------------------------------------------
__global__ void k_hist(const int* __restrict__ edst, int n_edges, int n_rows) {
    int e = blockIdx.x * blockDim.x + threadIdx.x;
    if (e >= n_edges) return;
    int d = edst[e];
    if ((unsigned)d < (unsigned)n_rows) atomicAdd(&g_cnt[d], 1);
}

// ---------------------------------------------------------------------------
// K2a: per-block inclusive scan of counts -> exclusive partials
// ---------------------------------------------------------------------------
__global__ void k_scan_partial(int n_rows) {
    __shared__ int s[256];
    int i = blockIdx.x * 256 + threadIdx.x;
    int c = (i < n_rows) ? g_cnt[i] : 0;
    s[threadIdx.x] = c;
    __syncthreads();
#pragma unroll
    for (int off = 1; off < 256; off <<= 1) {
        int t = (threadIdx.x >= off) ? s[threadIdx.x - off] : 0;
        __syncthreads();
        s[threadIdx.x] += t;
        __syncthreads();
    }
    if (i < n_rows) g_excl[i] = s[threadIdx.x] - c;
    if (threadIdx.x == 255) g_bsum[blockIdx.x] = s[255];
}

// ---------------------------------------------------------------------------
// K2b: scan block sums (single block, up to 1024 blocks)
// ---------------------------------------------------------------------------
__global__ void k_scan_tops(int nb) {
    __shared__ int s[1024];
    int t = threadIdx.x;
    int v = (t < nb) ? g_bsum[t] : 0;
    s[t] = v;
    __syncthreads();
#pragma unroll
    for (int off = 1; off < 1024; off <<= 1) {
        int u = (t >= off) ? s[t - off] : 0;
        __syncthreads();
        s[t] += u;
        __syncthreads();
    }
    if (t < nb) g_btop[t] = s[t] - v;   // exclusive
}

// ---------------------------------------------------------------------------
// K3: scatter edges into CSR slots (rowptr computed inline)
// ---------------------------------------------------------------------------
__global__ void k_scatter(const int* __restrict__ esrc,
                          const int* __restrict__ edst,
                          const float* __restrict__ eval,
                          int n_edges, int n_rows) {
    int e = blockIdx.x * blockDim.x + threadIdx.x;
    if (e >= n_edges) return;
    int d = edst[e];
    if ((unsigned)d >= (unsigned)n_rows) return;
    int base = g_excl[d] + g_btop[d >> 8];
    int pos = base + atomicAdd(&g_woff2[d], 1);
    int s = esrc[e];
    if ((unsigned)s >= (unsigned)n_rows) s = 0;
    g_csr[pos] = make_int2(s, __float_as_int(eval[e]));
}

// ---------------------------------------------------------------------------
// K4: GEMM y = x @ W. Full-K smem, one sync, f32x2 packed FMA.
// ---------------------------------------------------------------------------
#define MT 128
#define PAD 132
#define GEMM_SMEM (2 * 128 * PAD * sizeof(float))   // 135168 B

__global__ __launch_bounds__(256) void k_gemm_xw(const float* __restrict__ X,
                                                 const float* __restrict__ W,
                                                 int n_rows) {
    extern __shared__ float smem[];
    float* sA = smem;                 // 128 x PAD
    float* sW = smem + 128 * PAD;     // 128 x PAD

    float* Y = (float*)g_y4;

    int tid = threadIdx.x;
    int tx = tid & 15;
    int ty = tid >> 4;
    int row0 = blockIdx.x * MT + ty * 8;
    int c0 = tx * 8;

#pragma unroll
    for (int q = 0; q < 16; q++) {
        int f = tid + 256 * q;
        int r = f >> 5;
        int kq = f & 31;
        int grow = blockIdx.x * MT + r;
        float4 v = make_float4(0.f, 0.f, 0.f, 0.f);
        if (grow < n_rows)
            v = *reinterpret_cast<const float4*>(&X[(size_t)grow * D + kq * 4]);
        *reinterpret_cast<float4*>(&sA[r * PAD + kq * 4]) = v;
        float4 w = *reinterpret_cast<const float4*>(&W[(size_t)r * D + kq * 4]);
        *reinterpret_cast<float4*>(&sW[r * PAD + kq * 4]) = w;
    }
    __syncthreads();

    unsigned long long acc2[8][4];
#pragma unroll
    for (int i = 0; i < 8; i++)
#pragma unroll
        for (int j = 0; j < 4; j++) acc2[i][j] = 0ULL;

#pragma unroll 8
    for (int kk = 0; kk < D; kk++) {
        unsigned long long aa[8];
#pragma unroll
        for (int i = 0; i < 8; i++) {
            float a = sA[(ty * 8 + i) * PAD + kk];
            aa[i] = pack2(a, a);
        }
        float4 w0 = *reinterpret_cast<const float4*>(&sW[kk * PAD + c0]);
        float4 w1 = *reinterpret_cast<const float4*>(&sW[kk * PAD + c0 + 4]);
        unsigned long long wp[4];
        wp[0] = pack2(w0.x, w0.y);
        wp[1] = pack2(w0.z, w0.w);
        wp[2] = pack2(w1.x, w1.y);
        wp[3] = pack2(w1.z, w1.w);
#pragma unroll
        for (int i = 0; i < 8; i++)
#pragma unroll
            for (int j = 0; j < 4; j++) ffma2(acc2[i][j], aa[i], wp[j]);
    }

#pragma unroll
    for (int i = 0; i < 8; i++) {
        int row = row0 + i;
        if (row < n_rows) {
            float h[8];
#pragma unroll
            for (int j = 0; j < 4; j++)
                unpack2(acc2[i][j], h[2 * j], h[2 * j + 1]);
            float4 o0 = make_float4(h[0], h[1], h[2], h[3]);
            float4 o1 = make_float4(h[4], h[5], h[6], h[7]);
            *reinterpret_cast<float4*>(&Y[(size_t)row * D + c0]) = o0;
            *reinterpret_cast<float4*>(&Y[(size_t)row * D + c0 + 4]) = o1;
        }
    }
}

// ---------------------------------------------------------------------------
// K5: gather-reduce over y -> z rows (final h minus bias), fused BN stats.
// Grid-stride warp-per-node; lane owns one float4 chunk (4 columns).
// ---------------------------------------------------------------------------
__global__ __launch_bounds__(256) void k_gather(float4* __restrict__ out4,
                                                int n_rows, int total_warps) {
    __shared__ float s_sum[D];
    __shared__ float s_sq[D];
    if (threadIdx.x < D) { s_sum[threadIdx.x] = 0.f; s_sq[threadIdx.x] = 0.f; }
    __syncthreads();

    int gwarp = (blockIdx.x * blockDim.x + threadIdx.x) >> 5;
    int lane = threadIdx.x & 31;
    const float4* y4 = g_y4;

    float4 csum = make_float4(0.f, 0.f, 0.f, 0.f);
    float4 csq = make_float4(0.f, 0.f, 0.f, 0.f);

    for (int node = gwarp; node < n_rows; node += total_warps) {
        int start = g_excl[node] + g_btop[node >> 8];
        int deg = g_cnt[node];
        int end = start + deg;

        float4 acc = make_float4(0.f, 0.f, 0.f, 0.f);
        int p = start;
        for (; p + 3 < end; p += 4) {
            int2 e0 = g_csr[p];
            int2 e1 = g_csr[p + 1];
            int2 e2 = g_csr[p + 2];
            int2 e3 = g_csr[p + 3];
            float4 a = y4[(size_t)e0.x * 32 + lane];
            float4 b = y4[(size_t)e1.x * 32 + lane];
            float4 c = y4[(size_t)e2.x * 32 + lane];
            float4 d = y4[(size_t)e3.x * 32 + lane];
            float v0 = __int_as_float(e0.y);
            float v1 = __int_as_float(e1.y);
            float v2 = __int_as_float(e2.y);
            float v3 = __int_as_float(e3.y);
            acc.x += a.x * v0 + b.x * v1 + c.x * v2 + d.x * v3;
            acc.y += a.y * v0 + b.y * v1 + c.y * v2 + d.y * v3;
            acc.z += a.z * v0 + b.z * v1 + c.z * v2 + d.z * v3;
            acc.w += a.w * v0 + b.w * v1 + c.w * v2 + d.w * v3;
        }
        for (; p < end; p++) {
            int2 e0 = g_csr[p];
            float4 a = y4[(size_t)e0.x * 32 + lane];
            float v0 = __int_as_float(e0.y);
            acc.x += a.x * v0;
            acc.y += a.y * v0;
            acc.z += a.z * v0;
            acc.w += a.w * v0;
        }
        out4[(size_t)node * 32 + lane] = acc;
        csum.x += acc.x; csum.y += acc.y; csum.z += acc.z; csum.w += acc.w;
        csq.x += acc.x * acc.x; csq.y += acc.y * acc.y;
        csq.z += acc.z * acc.z; csq.w += acc.w * acc.w;
    }

    // per-block smem reduction of column stats
    int c0 = lane * 4;
    atomicAdd(&s_sum[c0 + 0], csum.x);
    atomicAdd(&s_sum[c0 + 1], csum.y);
    atomicAdd(&s_sum[c0 + 2], csum.z);
    atomicAdd(&s_sum[c0 + 3], csum.w);
    atomicAdd(&s_sq[c0 + 0], csq.x);
    atomicAdd(&s_sq[c0 + 1], csq.y);
    atomicAdd(&s_sq[c0 + 2], csq.z);
    atomicAdd(&s_sq[c0 + 3], csq.w);
    __syncthreads();
    if (threadIdx.x < D) {
        atomicAdd(&g_stats[threadIdx.x], s_sum[threadIdx.x]);
        atomicAdd(&g_stats[D + threadIdx.x], s_sq[threadIdx.x]);
    }
}

// ---------------------------------------------------------------------------
// K6: normalize in place. Bias cancels in BN, so stats are over z directly.
// ---------------------------------------------------------------------------
__global__ __launch_bounds__(256) void k_norm(float4* __restrict__ out,
                                              const float* __restrict__ gamma,
                                              const float* __restrict__ beta,
                                              float inv_n, int n_rows) {
    __shared__ float s_scale[D];
    __shared__ float s_shift[D];
    if (threadIdx.x < D) {
        int c = threadIdx.x;
        float mean = g_stats[c] * inv_n;
        float var = g_stats[D + c] * inv_n - mean * mean;
        float inv = rsqrtf(var + BN_EPS);
        float sc = gamma[c] * inv;
        s_scale[c] = sc;
        s_shift[c] = beta[c] - mean * sc;
    }
    __syncthreads();

    size_t total = (size_t)n_rows * (D / 4);
    size_t stride = (size_t)gridDim.x * blockDim.x;
    for (size_t i = (size_t)blockIdx.x * blockDim.x + threadIdx.x; i < total;
         i += stride) {
        int c4 = (int)(i & 31);
        float4 v = out[i];
        float4 sc = reinterpret_cast<const float4*>(s_scale)[c4];
        float4 sh = reinterpret_cast<const float4*>(s_shift)[c4];
        v.x = v.x * sc.x + sh.x;
        v.y = v.y * sc.y + sh.y;
        v.z = v.z * sc.z + sh.z;
        v.w = v.w * sc.w + sh.w;
        out[i] = v;
    }
}

// ---------------------------------------------------------------------------
extern "C" void kernel_launch(void* const* d_in, const int* in_sizes, int n_in,
                              void* d_out, int out_size) {
    const float* x    = (const float*)d_in[0];
    const int*   esrc = (const int*)d_in[1];
    const int*   edst = (const int*)d_in[2];
    const float* eval = (const float*)d_in[3];
    const float* W    = (const float*)d_in[4];
    // d_in[5] = bias: cancels analytically in BatchNorm — unused.
    const float* gamm = (const float*)d_in[6];
    const float* beta = (const float*)d_in[7];
    float* out = (float*)d_out;

    int n_rows = in_sizes[0] / D;      // 100000
    int n_edges = in_sizes[1];         // 1600000
    int nb = (n_rows + 255) / 256;     // scan blocks (<=1024)

    // One-time resource setup (same work every call; no cached results).
    static cudaStream_t s2 = nullptr;
    static cudaEvent_t ev_fork = nullptr, ev_join = nullptr;
    if (s2 == nullptr) {
        cudaFuncSetAttribute(k_gemm_xw, cudaFuncAttributeMaxDynamicSharedMemorySize,
                             (int)GEMM_SMEM);
        cudaStreamCreateWithFlags(&s2, cudaStreamNonBlocking);
        cudaEventCreateWithFlags(&ev_fork, cudaEventDisableTiming);
        cudaEventCreateWithFlags(&ev_join, cudaEventDisableTiming);
    }

    // Fork: GEMM (y = x@W) on s2, concurrent with CSR build on default stream.
    cudaEventRecord(ev_fork, 0);
    cudaStreamWaitEvent(s2, ev_fork, 0);
    k_gemm_xw<<<(n_rows + MT - 1) / MT, 256, GEMM_SMEM, s2>>>(x, W, n_rows);
    cudaEventRecord(ev_join, s2);

    // CSR build on default stream.
    k_zero_small<<<nb, 256>>>(n_rows);
    k_hist<<<(n_edges + 255) / 256, 256>>>(edst, n_edges, n_rows);
    k_scan_partial<<<nb, 256>>>(n_rows);
    k_scan_tops<<<1, 1024>>>(nb);
    k_scatter<<<(n_edges + 255) / 256, 256>>>(esrc, edst, eval, n_edges, n_rows);

    // Join: gather needs both y and CSR.
    cudaStreamWaitEvent(0, ev_join, 0);

    {
        int blocks = 1184;               // 8 blocks/SM
        int total_warps = blocks * (256 / 32);
        k_gather<<<blocks, 256>>>((float4*)out, n_rows, total_warps);
    }
    k_norm<<<1184, 256>>>((float4*)out, gamm, beta, 1.0f / (float)n_rows, n_rows);
}

// round 7
// speedup vs baseline: 1.8443x; 1.0963x over previous
#include <cuda_runtime.h>
#include <cuda_fp16.h>

#define N_NODES 100000
#define E_EDGES 1600000
#define D 128
#define BN_EPS 1e-5f
#define MAX_N 131072
#define MAX_E 2097152

// Scratch (static device globals — allocation-free).
__device__ __half g_yh[(size_t)N_NODES * D];   // 25.6 MB: y = x @ W in fp16
__device__ int    g_cnt[MAX_N];         // per-dst degree
__device__ int    g_excl[MAX_N];        // within-block exclusive scan
__device__ int    g_woff2[MAX_N];       // scatter cursor (from 0)
__device__ int    g_bsum[1024];         // block sums for scan
__device__ int    g_btop[1024];         // scanned block sums (exclusive)
__device__ int2   g_csr[MAX_E];         // packed (src, val-bits)
__device__ float  g_stats[2 * D];       // colsum / colsumsq of z

// ---------------- bit-reinterpret helpers ----------------
__device__ __forceinline__ unsigned int h2_as_u32(__half2 h) {
    return *reinterpret_cast<unsigned int*>(&h);
}
__device__ __forceinline__ __half2 u32_as_h2(unsigned int u) {
    return *reinterpret_cast<__half2*>(&u);
}

// ---------------- f32x2 packed-FMA helpers ----------------
__device__ __forceinline__ unsigned long long pack2(float lo, float hi) {
    unsigned long long r;
    asm("mov.b64 %0, {%1, %2};" : "=l"(r) : "f"(lo), "f"(hi));
    return r;
}
__device__ __forceinline__ void unpack2(unsigned long long v, float& lo, float& hi) {
    asm("mov.b64 {%0, %1}, %2;" : "=f"(lo), "=f"(hi) : "l"(v));
}
__device__ __forceinline__ void ffma2(unsigned long long& d,
                                      unsigned long long a,
                                      unsigned long long b) {
    asm("fma.rn.f32x2 %0, %1, %2, %0;" : "+l"(d) : "l"(a), "l"(b));
}

// ---------------------------------------------------------------------------
// K0: zero degree counters + cursors + stats
// ---------------------------------------------------------------------------
__global__ void k_zero_small(int n_rows) {
    int i = blockIdx.x * blockDim.x + threadIdx.x;
    if (i < n_rows) { g_cnt[i] = 0; g_woff2[i] = 0; }
    if (blockIdx.x == 0 && threadIdx.x < 2 * D) g_stats[threadIdx.x] = 0.f;
}

// ---------------------------------------------------------------------------
// K1: histogram of dst (4 edges per thread, vectorized load)
// ---------------------------------------------------------------------------
__global__ void k_hist(const int4* __restrict__ edst4, int n_e4, int n_rows) {
    int i = blockIdx.x * blockDim.x + threadIdx.x;
    if (i >= n_e4) return;
    int4 d = edst4[i];
    if ((unsigned)d.x < (unsigned)n_rows) atomicAdd(&g_cnt[d.x], 1);
    if ((unsigned)d.y < (unsigned)n_rows) atomicAdd(&g_cnt[d.y], 1);
    if ((unsigned)d.z < (unsigned)n_rows) atomicAdd(&g_cnt[d.z], 1);
    if ((unsigned)d.w < (unsigned)n_rows) atomicAdd(&g_cnt[d.w], 1);
}

// ---------------------------------------------------------------------------
// K2a: per-block inclusive scan of counts -> exclusive partials
// ---------------------------------------------------------------------------
__global__ void k_scan_partial(int n_rows) {
    __shared__ int s[256];
    int i = blockIdx.x * 256 + threadIdx.x;
    int c = (i < n_rows) ? g_cnt[i] : 0;
    s[threadIdx.x] = c;
    __syncthreads();
#pragma unroll
    for (int off = 1; off < 256; off <<= 1) {
        int t = (threadIdx.x >= off) ? s[threadIdx.x - off] : 0;
        __syncthreads();
        s[threadIdx.x] += t;
        __syncthreads();
    }
    if (i < n_rows) g_excl[i] = s[threadIdx.x] - c;
    if (threadIdx.x == 255) g_bsum[blockIdx.x] = s[255];
}

// ---------------------------------------------------------------------------
// K2b: scan block sums (single block, up to 1024 blocks)
// ---------------------------------------------------------------------------
__global__ void k_scan_tops(int nb) {
    __shared__ int s[1024];
    int t = threadIdx.x;
    int v = (t < nb) ? g_bsum[t] : 0;
    s[t] = v;
    __syncthreads();
#pragma unroll
    for (int off = 1; off < 1024; off <<= 1) {
        int u = (t >= off) ? s[t - off] : 0;
        __syncthreads();
        s[t] += u;
        __syncthreads();
    }
    if (t < nb) g_btop[t] = s[t] - v;   // exclusive
}

// ---------------------------------------------------------------------------
// K3: scatter edges into CSR slots (rowptr computed inline)
// ---------------------------------------------------------------------------
__global__ void k_scatter(const int* __restrict__ esrc,
                          const int* __restrict__ edst,
                          const float* __restrict__ eval,
                          int n_edges, int n_rows) {
    int e = blockIdx.x * blockDim.x + threadIdx.x;
    if (e >= n_edges) return;
    int d = edst[e];
    if ((unsigned)d >= (unsigned)n_rows) return;
    int base = g_excl[d] + g_btop[d >> 8];
    int pos = base + atomicAdd(&g_woff2[d], 1);
    int s = esrc[e];
    if ((unsigned)s >= (unsigned)n_rows) s = 0;
    g_csr[pos] = make_int2(s, __float_as_int(eval[e]));
}

// ---------------------------------------------------------------------------
// K4: GEMM y = x @ W (fp32 compute, fp16 output). Full-K smem, one sync.
// ---------------------------------------------------------------------------
#define MT 128
#define PAD 132
#define GEMM_SMEM (2 * 128 * PAD * sizeof(float))   // 135168 B

__global__ __launch_bounds__(256) void k_gemm_xw(const float* __restrict__ X,
                                                 const float* __restrict__ W,
                                                 int n_rows) {
    extern __shared__ float smem[];
    float* sA = smem;                 // 128 x PAD
    float* sW = smem + 128 * PAD;     // 128 x PAD

    __half* Y = g_yh;

    int tid = threadIdx.x;
    int tx = tid & 15;
    int ty = tid >> 4;
    int row0 = blockIdx.x * MT + ty * 8;
    int c0 = tx * 8;

#pragma unroll
    for (int q = 0; q < 16; q++) {
        int f = tid + 256 * q;
        int r = f >> 5;
        int kq = f & 31;
        int grow = blockIdx.x * MT + r;
        float4 v = make_float4(0.f, 0.f, 0.f, 0.f);
        if (grow < n_rows)
            v = *reinterpret_cast<const float4*>(&X[(size_t)grow * D + kq * 4]);
        *reinterpret_cast<float4*>(&sA[r * PAD + kq * 4]) = v;
        float4 w = *reinterpret_cast<const float4*>(&W[(size_t)r * D + kq * 4]);
        *reinterpret_cast<float4*>(&sW[r * PAD + kq * 4]) = w;
    }
    __syncthreads();

    unsigned long long acc2[8][4];
#pragma unroll
    for (int i = 0; i < 8; i++)
#pragma unroll
        for (int j = 0; j < 4; j++) acc2[i][j] = 0ULL;

#pragma unroll 8
    for (int kk = 0; kk < D; kk++) {
        unsigned long long aa[8];
#pragma unroll
        for (int i = 0; i < 8; i++) {
            float a = sA[(ty * 8 + i) * PAD + kk];
            aa[i] = pack2(a, a);
        }
        float4 w0 = *reinterpret_cast<const float4*>(&sW[kk * PAD + c0]);
        float4 w1 = *reinterpret_cast<const float4*>(&sW[kk * PAD + c0 + 4]);
        unsigned long long wp[4];
        wp[0] = pack2(w0.x, w0.y);
        wp[1] = pack2(w0.z, w0.w);
        wp[2] = pack2(w1.x, w1.y);
        wp[3] = pack2(w1.z, w1.w);
#pragma unroll
        for (int i = 0; i < 8; i++)
#pragma unroll
            for (int j = 0; j < 4; j++) ffma2(acc2[i][j], aa[i], wp[j]);
    }

#pragma unroll
    for (int i = 0; i < 8; i++) {
        int row = row0 + i;
        if (row < n_rows) {
            float h[8];
#pragma unroll
            for (int j = 0; j < 4; j++)
                unpack2(acc2[i][j], h[2 * j], h[2 * j + 1]);
            __half2 p0 = __float22half2_rn(make_float2(h[0], h[1]));
            __half2 p1 = __float22half2_rn(make_float2(h[2], h[3]));
            __half2 p2 = __float22half2_rn(make_float2(h[4], h[5]));
            __half2 p3 = __float22half2_rn(make_float2(h[6], h[7]));
            uint4 o;
            o.x = h2_as_u32(p0); // 8 halfs = 16B per thread
            o.y = h2_as_u32(p1);
            o.z = h2_as_u32(p2);
            o.w = h2_as_u32(p3);
            *reinterpret_cast<uint4*>(&Y[(size_t)row * D + c0]) = o;
        }
    }
}

// ---------------------------------------------------------------------------
// K5: gather-reduce over fp16 y -> fp32 z rows, fused BN stats.
// Grid-stride warp-per-node; lane owns 4 columns (one uint2 = 4 halfs).
// ---------------------------------------------------------------------------
__global__ __launch_bounds__(256) void k_gather(float4* __restrict__ out4,
                                                int n_rows, int total_warps) {
    __shared__ float s_sum[D];
    __shared__ float s_sq[D];
    if (threadIdx.x < D) { s_sum[threadIdx.x] = 0.f; s_sq[threadIdx.x] = 0.f; }
    __syncthreads();

    int gwarp = (blockIdx.x * blockDim.x + threadIdx.x) >> 5;
    int lane = threadIdx.x & 31;
    const uint2* y2 = reinterpret_cast<const uint2*>(g_yh);  // 32 uint2 per row

    float4 csum = make_float4(0.f, 0.f, 0.f, 0.f);
    float4 csq = make_float4(0.f, 0.f, 0.f, 0.f);

    for (int node = gwarp; node < n_rows; node += total_warps) {
        int start = g_excl[node] + g_btop[node >> 8];
        int deg = g_cnt[node];
        int end = start + deg;

        float4 acc = make_float4(0.f, 0.f, 0.f, 0.f);
        int p = start;
        for (; p + 3 < end; p += 4) {
            int2 e0 = g_csr[p];
            int2 e1 = g_csr[p + 1];
            int2 e2 = g_csr[p + 2];
            int2 e3 = g_csr[p + 3];
            uint2 ra = y2[(size_t)e0.x * 32 + lane];
            uint2 rb = y2[(size_t)e1.x * 32 + lane];
            uint2 rc = y2[(size_t)e2.x * 32 + lane];
            uint2 rd = y2[(size_t)e3.x * 32 + lane];
            float v0 = __int_as_float(e0.y);
            float v1 = __int_as_float(e1.y);
            float v2 = __int_as_float(e2.y);
            float v3 = __int_as_float(e3.y);
            float2 a0 = __half22float2(u32_as_h2(ra.x));
            float2 a1 = __half22float2(u32_as_h2(ra.y));
            float2 b0 = __half22float2(u32_as_h2(rb.x));
            float2 b1 = __half22float2(u32_as_h2(rb.y));
            float2 c0f = __half22float2(u32_as_h2(rc.x));
            float2 c1 = __half22float2(u32_as_h2(rc.y));
            float2 d0 = __half22float2(u32_as_h2(rd.x));
            float2 d1 = __half22float2(u32_as_h2(rd.y));
            acc.x += a0.x * v0 + b0.x * v1 + c0f.x * v2 + d0.x * v3;
            acc.y += a0.y * v0 + b0.y * v1 + c0f.y * v2 + d0.y * v3;
            acc.z += a1.x * v0 + b1.x * v1 + c1.x * v2 + d1.x * v3;
            acc.w += a1.y * v0 + b1.y * v1 + c1.y * v2 + d1.y * v3;
        }
        for (; p < end; p++) {
            int2 e0 = g_csr[p];
            uint2 ra = y2[(size_t)e0.x * 32 + lane];
            float v0 = __int_as_float(e0.y);
            float2 a0 = __half22float2(u32_as_h2(ra.x));
            float2 a1 = __half22float2(u32_as_h2(ra.y));
            acc.x += a0.x * v0;
            acc.y += a0.y * v0;
            acc.z += a1.x * v0;
            acc.w += a1.y * v0;
        }
        out4[(size_t)node * 32 + lane] = acc;
        csum.x += acc.x; csum.y += acc.y; csum.z += acc.z; csum.w += acc.w;
        csq.x += acc.x * acc.x; csq.y += acc.y * acc.y;
        csq.z += acc.z * acc.z; csq.w += acc.w * acc.w;
    }

    // per-block smem reduction of column stats
    int c0 = lane * 4;
    atomicAdd(&s_sum[c0 + 0], csum.x);
    atomicAdd(&s_sum[c0 + 1], csum.y);
    atomicAdd(&s_sum[c0 + 2], csum.z);
    atomicAdd(&s_sum[c0 + 3], csum.w);
    atomicAdd(&s_sq[c0 + 0], csq.x);
    atomicAdd(&s_sq[c0 + 1], csq.y);
    atomicAdd(&s_sq[c0 + 2], csq.z);
    atomicAdd(&s_sq[c0 + 3], csq.w);
    __syncthreads();
    if (threadIdx.x < D) {
        atomicAdd(&g_stats[threadIdx.x], s_sum[threadIdx.x]);
        atomicAdd(&g_stats[D + threadIdx.x], s_sq[threadIdx.x]);
    }
}

// ---------------------------------------------------------------------------
// K6: normalize in place. Bias cancels in BN.
// ---------------------------------------------------------------------------
__global__ __launch_bounds__(256) void k_norm(float4* __restrict__ out,
                                              const float* __restrict__ gamma,
                                              const float* __restrict__ beta,
                                              float inv_n, int n_rows) {
    __shared__ float s_scale[D];
    __shared__ float s_shift[D];
    if (threadIdx.x < D) {
        int c = threadIdx.x;
        float mean = g_stats[c] * inv_n;
        float var = g_stats[D + c] * inv_n - mean * mean;
        float inv = rsqrtf(var + BN_EPS);
        float sc = gamma[c] * inv;
        s_scale[c] = sc;
        s_shift[c] = beta[c] - mean * sc;
    }
    __syncthreads();

    size_t total = (size_t)n_rows * (D / 4);
    size_t stride = (size_t)gridDim.x * blockDim.x;
    for (size_t i = (size_t)blockIdx.x * blockDim.x + threadIdx.x; i < total;
         i += stride) {
        int c4 = (int)(i & 31);
        float4 v = out[i];
        float4 sc = reinterpret_cast<const float4*>(s_scale)[c4];
        float4 sh = reinterpret_cast<const float4*>(s_shift)[c4];
        v.x = v.x * sc.x + sh.x;
        v.y = v.y * sc.y + sh.y;
        v.z = v.z * sc.z + sh.z;
        v.w = v.w * sc.w + sh.w;
        out[i] = v;
    }
}

// ---------------------------------------------------------------------------
extern "C" void kernel_launch(void* const* d_in, const int* in_sizes, int n_in,
                              void* d_out, int out_size) {
    const float* x    = (const float*)d_in[0];
    const int*   esrc = (const int*)d_in[1];
    const int*   edst = (const int*)d_in[2];
    const float* eval = (const float*)d_in[3];
    const float* W    = (const float*)d_in[4];
    // d_in[5] = bias: cancels analytically in BatchNorm — unused.
    const float* gamm = (const float*)d_in[6];
    const float* beta = (const float*)d_in[7];
    float* out = (float*)d_out;

    int n_rows = in_sizes[0] / D;      // 100000
    int n_edges = in_sizes[1];         // 1600000
    int nb = (n_rows + 255) / 256;     // scan blocks (<=1024)

    // One-time resource setup (same work every call; no cached results).
    static cudaStream_t s2 = nullptr;
    static cudaEvent_t ev_fork = nullptr, ev_join = nullptr;
    if (s2 == nullptr) {
        cudaFuncSetAttribute(k_gemm_xw, cudaFuncAttributeMaxDynamicSharedMemorySize,
                             (int)GEMM_SMEM);
        cudaStreamCreateWithFlags(&s2, cudaStreamNonBlocking);
        cudaEventCreateWithFlags(&ev_fork, cudaEventDisableTiming);
        cudaEventCreateWithFlags(&ev_join, cudaEventDisableTiming);
    }

    // Fork: GEMM (y = x@W, fp16 out) on s2, concurrent with CSR build.
    cudaEventRecord(ev_fork, 0);
    cudaStreamWaitEvent(s2, ev_fork, 0);
    k_gemm_xw<<<(n_rows + MT - 1) / MT, 256, GEMM_SMEM, s2>>>(x, W, n_rows);
    cudaEventRecord(ev_join, s2);

    // CSR build on default stream.
    k_zero_small<<<nb, 256>>>(n_rows);
    k_hist<<<(n_edges / 4 + 255) / 256, 256>>>((const int4*)edst, n_edges / 4,
                                               n_rows);
    k_scan_partial<<<nb, 256>>>(n_rows);
    k_scan_tops<<<1, 1024>>>(nb);
    k_scatter<<<(n_edges + 255) / 256, 256>>>(esrc, edst, eval, n_edges, n_rows);

    // Join: gather needs both y and CSR.
    cudaStreamWaitEvent(0, ev_join, 0);

    {
        int blocks = 1184;               // 8 blocks/SM
        int total_warps = blocks * (256 / 32);
        k_gather<<<blocks, 256>>>((float4*)out, n_rows, total_warps);
    }
    k_norm<<<1184, 256>>>((float4*)out, gamm, beta, 1.0f / (float)n_rows, n_rows);
}

// round 8
// speedup vs baseline: 1.9541x; 1.0595x over previous
#include <cuda_runtime.h>
#include <cuda_fp16.h>

#define N_NODES 100000
#define E_EDGES 1600000
#define D 128
#define BN_EPS 1e-5f
#define MAX_N 131072
#define MAX_E 2097152

// Scratch (static device globals — allocation-free).
__device__ __half g_yh[(size_t)N_NODES * D];   // 25.6 MB: y = x @ W in fp16
__device__ int    g_cnt[MAX_N];         // per-dst degree
__device__ int    g_excl[MAX_N];        // within-block exclusive scan
__device__ int    g_woff2[MAX_N];       // scatter cursor (from 0)
__device__ int    g_bsum[1024];         // block sums for scan
__device__ int    g_btop[1024];         // scanned block sums (exclusive)
__device__ int2   g_csr[MAX_E];         // packed (src, val-bits)
__device__ float  g_stats[2 * D];       // colsum / colsumsq of z

// ---------------- bit-reinterpret helpers ----------------
__device__ __forceinline__ unsigned int h2_as_u32(__half2 h) {
    return *reinterpret_cast<unsigned int*>(&h);
}
__device__ __forceinline__ __half2 u32_as_h2(unsigned int u) {
    return *reinterpret_cast<__half2*>(&u);
}

// ---------------- f32x2 packed-FMA helpers ----------------
__device__ __forceinline__ unsigned long long pack2(float lo, float hi) {
    unsigned long long r;
    asm("mov.b64 %0, {%1, %2};" : "=l"(r) : "f"(lo), "f"(hi));
    return r;
}
__device__ __forceinline__ void unpack2(unsigned long long v, float& lo, float& hi) {
    asm("mov.b64 {%0, %1}, %2;" : "=f"(lo), "=f"(hi) : "l"(v));
}
__device__ __forceinline__ void ffma2(unsigned long long& d,
                                      unsigned long long a,
                                      unsigned long long b) {
    asm("fma.rn.f32x2 %0, %1, %2, %0;" : "+l"(d) : "l"(a), "l"(b));
}

// ---------------------------------------------------------------------------
// K0: zero degree counters + cursors + stats
// ---------------------------------------------------------------------------
__global__ void k_zero_small(int n_rows) {
    int i = blockIdx.x * blockDim.x + threadIdx.x;
    if (i < n_rows) { g_cnt[i] = 0; g_woff2[i] = 0; }
    if (blockIdx.x == 0 && threadIdx.x < 2 * D) g_stats[threadIdx.x] = 0.f;
}

// ---------------------------------------------------------------------------
// K1: histogram of dst (4 edges per thread, vectorized load)
// ---------------------------------------------------------------------------
__global__ void k_hist(const int4* __restrict__ edst4, int n_e4, int n_rows) {
    int i = blockIdx.x * blockDim.x + threadIdx.x;
    if (i >= n_e4) return;
    int4 d = edst4[i];
    if ((unsigned)d.x < (unsigned)n_rows) atomicAdd(&g_cnt[d.x], 1);
    if ((unsigned)d.y < (unsigned)n_rows) atomicAdd(&g_cnt[d.y], 1);
    if ((unsigned)d.z < (unsigned)n_rows) atomicAdd(&g_cnt[d.z], 1);
    if ((unsigned)d.w < (unsigned)n_rows) atomicAdd(&g_cnt[d.w], 1);
}

// ---------------------------------------------------------------------------
// K2a: per-block inclusive scan of counts -> exclusive partials
// ---------------------------------------------------------------------------
__global__ void k_scan_partial(int n_rows) {
    __shared__ int s[256];
    int i = blockIdx.x * 256 + threadIdx.x;
    int c = (i < n_rows) ? g_cnt[i] : 0;
    s[threadIdx.x] = c;
    __syncthreads();
#pragma unroll
    for (int off = 1; off < 256; off <<= 1) {
        int t = (threadIdx.x >= off) ? s[threadIdx.x - off] : 0;
        __syncthreads();
        s[threadIdx.x] += t;
        __syncthreads();
    }
    if (i < n_rows) g_excl[i] = s[threadIdx.x] - c;
    if (threadIdx.x == 255) g_bsum[blockIdx.x] = s[255];
}

// ---------------------------------------------------------------------------
// K2b: scan block sums (single block, up to 512 blocks)
// ---------------------------------------------------------------------------
__global__ void k_scan_tops(int nb) {
    __shared__ int s[512];
    int t = threadIdx.x;
    int v = (t < nb) ? g_bsum[t] : 0;
    s[t] = v;
    __syncthreads();
#pragma unroll
    for (int off = 1; off < 512; off <<= 1) {
        int u = (t >= off) ? s[t - off] : 0;
        __syncthreads();
        s[t] += u;
        __syncthreads();
    }
    if (t < nb) g_btop[t] = s[t] - v;   // exclusive
}

// ---------------------------------------------------------------------------
// K3: scatter edges into CSR slots (2 edges per thread, vector loads)
// ---------------------------------------------------------------------------
__global__ void k_scatter(const int2* __restrict__ esrc2,
                          const int2* __restrict__ edst2,
                          const float2* __restrict__ eval2,
                          int n_e2, int n_rows) {
    int i = blockIdx.x * blockDim.x + threadIdx.x;
    if (i >= n_e2) return;
    int2 d = edst2[i];
    int2 s = esrc2[i];
    float2 v = eval2[i];
    if ((unsigned)d.x < (unsigned)n_rows) {
        int base = g_excl[d.x] + g_btop[d.x >> 8];
        int pos = base + atomicAdd(&g_woff2[d.x], 1);
        int ss = ((unsigned)s.x < (unsigned)n_rows) ? s.x : 0;
        g_csr[pos] = make_int2(ss, __float_as_int(v.x));
    }
    if ((unsigned)d.y < (unsigned)n_rows) {
        int base = g_excl[d.y] + g_btop[d.y >> 8];
        int pos = base + atomicAdd(&g_woff2[d.y], 1);
        int ss = ((unsigned)s.y < (unsigned)n_rows) ? s.y : 0;
        g_csr[pos] = make_int2(ss, __float_as_int(v.y));
    }
}

// ---------------------------------------------------------------------------
// K4: GEMM y = x @ W (fp32 compute, fp16 output). Full-K smem, one sync.
// ---------------------------------------------------------------------------
#define MT 128
#define PAD 132
#define GEMM_SMEM (2 * 128 * PAD * sizeof(float))   // 135168 B

__global__ __launch_bounds__(256) void k_gemm_xw(const float* __restrict__ X,
                                                 const float* __restrict__ W,
                                                 int n_rows) {
    extern __shared__ float smem[];
    float* sA = smem;                 // 128 x PAD
    float* sW = smem + 128 * PAD;     // 128 x PAD

    __half* Y = g_yh;

    int tid = threadIdx.x;
    int tx = tid & 15;
    int ty = tid >> 4;
    int row0 = blockIdx.x * MT + ty * 8;
    int c0 = tx * 8;

#pragma unroll
    for (int q = 0; q < 16; q++) {
        int f = tid + 256 * q;
        int r = f >> 5;
        int kq = f & 31;
        int grow = blockIdx.x * MT + r;
        float4 v = make_float4(0.f, 0.f, 0.f, 0.f);
        if (grow < n_rows)
            v = *reinterpret_cast<const float4*>(&X[(size_t)grow * D + kq * 4]);
        *reinterpret_cast<float4*>(&sA[r * PAD + kq * 4]) = v;
        float4 w = *reinterpret_cast<const float4*>(&W[(size_t)r * D + kq * 4]);
        *reinterpret_cast<float4*>(&sW[r * PAD + kq * 4]) = w;
    }
    __syncthreads();

    unsigned long long acc2[8][4];
#pragma unroll
    for (int i = 0; i < 8; i++)
#pragma unroll
        for (int j = 0; j < 4; j++) acc2[i][j] = 0ULL;

#pragma unroll 8
    for (int kk = 0; kk < D; kk++) {
        unsigned long long aa[8];
#pragma unroll
        for (int i = 0; i < 8; i++) {
            float a = sA[(ty * 8 + i) * PAD + kk];
            aa[i] = pack2(a, a);
        }
        float4 w0 = *reinterpret_cast<const float4*>(&sW[kk * PAD + c0]);
        float4 w1 = *reinterpret_cast<const float4*>(&sW[kk * PAD + c0 + 4]);
        unsigned long long wp[4];
        wp[0] = pack2(w0.x, w0.y);
        wp[1] = pack2(w0.z, w0.w);
        wp[2] = pack2(w1.x, w1.y);
        wp[3] = pack2(w1.z, w1.w);
#pragma unroll
        for (int i = 0; i < 8; i++)
#pragma unroll
            for (int j = 0; j < 4; j++) ffma2(acc2[i][j], aa[i], wp[j]);
    }

#pragma unroll
    for (int i = 0; i < 8; i++) {
        int row = row0 + i;
        if (row < n_rows) {
            float h[8];
#pragma unroll
            for (int j = 0; j < 4; j++)
                unpack2(acc2[i][j], h[2 * j], h[2 * j + 1]);
            __half2 p0 = __float22half2_rn(make_float2(h[0], h[1]));
            __half2 p1 = __float22half2_rn(make_float2(h[2], h[3]));
            __half2 p2 = __float22half2_rn(make_float2(h[4], h[5]));
            __half2 p3 = __float22half2_rn(make_float2(h[6], h[7]));
            uint4 o;
            o.x = h2_as_u32(p0);
            o.y = h2_as_u32(p1);
            o.z = h2_as_u32(p2);
            o.w = h2_as_u32(p3);
            *reinterpret_cast<uint4*>(&Y[(size_t)row * D + c0]) = o;
        }
    }
}

// ---------------------------------------------------------------------------
// K5: gather-reduce over fp16 y -> fp32 z rows, fused BN stats.
// Grid-stride warp-per-node; lane owns 4 columns. 8-edge unroll for MLP.
// ---------------------------------------------------------------------------
__device__ __forceinline__ void acc_edge(float4& acc, uint2 r, float v) {
    float2 a0 = __half22float2(u32_as_h2(r.x));
    float2 a1 = __half22float2(u32_as_h2(r.y));
    acc.x += a0.x * v;
    acc.y += a0.y * v;
    acc.z += a1.x * v;
    acc.w += a1.y * v;
}

__global__ __launch_bounds__(256) void k_gather(float4* __restrict__ out4,
                                                int n_rows, int total_warps) {
    __shared__ float s_sum[D];
    __shared__ float s_sq[D];
    if (threadIdx.x < D) { s_sum[threadIdx.x] = 0.f; s_sq[threadIdx.x] = 0.f; }
    __syncthreads();

    int gwarp = (blockIdx.x * blockDim.x + threadIdx.x) >> 5;
    int lane = threadIdx.x & 31;
    const uint2* y2 = reinterpret_cast<const uint2*>(g_yh);  // 32 uint2 per row

    float4 csum = make_float4(0.f, 0.f, 0.f, 0.f);
    float4 csq = make_float4(0.f, 0.f, 0.f, 0.f);

    for (int node = gwarp; node < n_rows; node += total_warps) {
        int start = g_excl[node] + g_btop[node >> 8];
        int deg = g_cnt[node];
        int end = start + deg;

        float4 acc = make_float4(0.f, 0.f, 0.f, 0.f);
        int p = start;
        for (; p + 7 < end; p += 8) {
            int2 e[8];
#pragma unroll
            for (int q = 0; q < 8; q++) e[q] = g_csr[p + q];
            uint2 r[8];
#pragma unroll
            for (int q = 0; q < 8; q++)
                r[q] = y2[(size_t)e[q].x * 32 + lane];
#pragma unroll
            for (int q = 0; q < 8; q++)
                acc_edge(acc, r[q], __int_as_float(e[q].y));
        }
        for (; p + 3 < end; p += 4) {
            int2 e[4];
#pragma unroll
            for (int q = 0; q < 4; q++) e[q] = g_csr[p + q];
            uint2 r[4];
#pragma unroll
            for (int q = 0; q < 4; q++)
                r[q] = y2[(size_t)e[q].x * 32 + lane];
#pragma unroll
            for (int q = 0; q < 4; q++)
                acc_edge(acc, r[q], __int_as_float(e[q].y));
        }
        for (; p < end; p++) {
            int2 e0 = g_csr[p];
            uint2 ra = y2[(size_t)e0.x * 32 + lane];
            acc_edge(acc, ra, __int_as_float(e0.y));
        }
        out4[(size_t)node * 32 + lane] = acc;
        csum.x += acc.x; csum.y += acc.y; csum.z += acc.z; csum.w += acc.w;
        csq.x += acc.x * acc.x; csq.y += acc.y * acc.y;
        csq.z += acc.z * acc.z; csq.w += acc.w * acc.w;
    }

    // per-block smem reduction of column stats
    int c0 = lane * 4;
    atomicAdd(&s_sum[c0 + 0], csum.x);
    atomicAdd(&s_sum[c0 + 1], csum.y);
    atomicAdd(&s_sum[c0 + 2], csum.z);
    atomicAdd(&s_sum[c0 + 3], csum.w);
    atomicAdd(&s_sq[c0 + 0], csq.x);
    atomicAdd(&s_sq[c0 + 1], csq.y);
    atomicAdd(&s_sq[c0 + 2], csq.z);
    atomicAdd(&s_sq[c0 + 3], csq.w);
    __syncthreads();
    if (threadIdx.x < D) {
        atomicAdd(&g_stats[threadIdx.x], s_sum[threadIdx.x]);
        atomicAdd(&g_stats[D + threadIdx.x], s_sq[threadIdx.x]);
    }
}

// ---------------------------------------------------------------------------
// K6: normalize in place. Bias cancels in BN.
// ---------------------------------------------------------------------------
__global__ __launch_bounds__(256) void k_norm(float4* __restrict__ out,
                                              const float* __restrict__ gamma,
                                              const float* __restrict__ beta,
                                              float inv_n, int n_rows) {
    __shared__ float s_scale[D];
    __shared__ float s_shift[D];
    if (threadIdx.x < D) {
        int c = threadIdx.x;
        float mean = g_stats[c] * inv_n;
        float var = g_stats[D + c] * inv_n - mean * mean;
        float inv = rsqrtf(var + BN_EPS);
        float sc = gamma[c] * inv;
        s_scale[c] = sc;
        s_shift[c] = beta[c] - mean * sc;
    }
    __syncthreads();

    size_t total = (size_t)n_rows * (D / 4);
    size_t stride = (size_t)gridDim.x * blockDim.x;
    for (size_t i = (size_t)blockIdx.x * blockDim.x + threadIdx.x; i < total;
         i += stride) {
        int c4 = (int)(i & 31);
        float4 v = out[i];
        float4 sc = reinterpret_cast<const float4*>(s_scale)[c4];
        float4 sh = reinterpret_cast<const float4*>(s_shift)[c4];
        v.x = v.x * sc.x + sh.x;
        v.y = v.y * sc.y + sh.y;
        v.z = v.z * sc.z + sh.z;
        v.w = v.w * sc.w + sh.w;
        out[i] = v;
    }
}

// ---------------------------------------------------------------------------
extern "C" void kernel_launch(void* const* d_in, const int* in_sizes, int n_in,
                              void* d_out, int out_size) {
    const float* x    = (const float*)d_in[0];
    const int*   esrc = (const int*)d_in[1];
    const int*   edst = (const int*)d_in[2];
    const float* eval = (const float*)d_in[3];
    const float* W    = (const float*)d_in[4];
    // d_in[5] = bias: cancels analytically in BatchNorm — unused.
    const float* gamm = (const float*)d_in[6];
    const float* beta = (const float*)d_in[7];
    float* out = (float*)d_out;

    int n_rows = in_sizes[0] / D;      // 100000
    int n_edges = in_sizes[1];         // 1600000
    int nb = (n_rows + 255) / 256;     // scan blocks (<=512)

    // One-time resource setup (same work every call; no cached results).
    static cudaStream_t s2 = nullptr;
    static cudaEvent_t ev_fork = nullptr, ev_join = nullptr;
    if (s2 == nullptr) {
        cudaFuncSetAttribute(k_gemm_xw, cudaFuncAttributeMaxDynamicSharedMemorySize,
                             (int)GEMM_SMEM);
        cudaStreamCreateWithFlags(&s2, cudaStreamNonBlocking);
        cudaEventCreateWithFlags(&ev_fork, cudaEventDisableTiming);
        cudaEventCreateWithFlags(&ev_join, cudaEventDisableTiming);
    }

    // Fork: GEMM (y = x@W, fp16 out) on s2, concurrent with CSR build.
    cudaEventRecord(ev_fork, 0);
    cudaStreamWaitEvent(s2, ev_fork, 0);
    k_gemm_xw<<<(n_rows + MT - 1) / MT, 256, GEMM_SMEM, s2>>>(x, W, n_rows);
    cudaEventRecord(ev_join, s2);

    // CSR build on default stream.
    k_zero_small<<<nb, 256>>>(n_rows);
    k_hist<<<(n_edges / 4 + 255) / 256, 256>>>((const int4*)edst, n_edges / 4,
                                               n_rows);
    k_scan_partial<<<nb, 256>>>(n_rows);
    k_scan_tops<<<1, 512>>>(nb);
    k_scatter<<<(n_edges / 2 + 255) / 256, 256>>>((const int2*)esrc,
                                                  (const int2*)edst,
                                                  (const float2*)eval,
                                                  n_edges / 2, n_rows);

    // Join: gather needs both y and CSR.
    cudaStreamWaitEvent(0, ev_join, 0);

    {
        int blocks = 1184;               // 8 blocks/SM
        int total_warps = blocks * (256 / 32);
        k_gather<<<blocks, 256>>>((float4*)out, n_rows, total_warps);
    }
    k_norm<<<1184, 256>>>((float4*)out, gamm, beta, 1.0f / (float)n_rows, n_rows);
}